// round 16
// baseline (speedup 1.0000x reference)
#include <cuda_runtime.h>
#include <cuda_fp16.h>
#include <cstdint>
#include <math.h>

// ---------------------------------------------------------------------------
// Problem constants
// ---------------------------------------------------------------------------
constexpr int B = 4;
constexpr int S = 2048;
constexpr int E = 1024;
constexpr int M_ROWS = B * S;   // 8192

// GEMM tiling: CTA 128x256 (8 warps of 64x64), KB=64 fp16 per chunk
constexpr int TM = 128, TN = 256, KB = 64;
constexpr int NTHR = 256;
constexpr int A_TILE = 128 * 128;              // 16KB  (128 rows x 128B)
constexpr int B_TILE = 256 * 128;              // 32KB  (256 rows x 128B)
constexpr int STAGE_BYTES = 2 * A_TILE + B_TILE;   // Ah, Al, Bh = 64KB
constexpr int NSTAGE = 3;
constexpr int SMEM_SZ = NSTAGE * STAGE_BYTES;  // 192KB
constexpr int EPIT = 260;                      // fp32 epilogue pitch (words)

// ---------------------------------------------------------------------------
// Scratch (device globals — no allocations allowed)
// ---------------------------------------------------------------------------
__device__ __half g_qh[(size_t)M_ROWS * E], g_ql[(size_t)M_ROWS * E];
__device__ __half g_kh[(size_t)M_ROWS * E], g_kl[(size_t)M_ROWS * E];
__device__ __half g_vh[(size_t)M_ROWS * E], g_vl[(size_t)M_ROWS * E];
__device__ __half g_wqh[(size_t)E * E];
__device__ __half g_wkh[(size_t)E * E];
__device__ __half g_wvh[(size_t)E * E];
__device__ __half g_woh[(size_t)E * E];
__device__ __half g_Qh[(size_t)M_ROWS * E], g_Ql[(size_t)M_ROWS * E];
__device__ __half g_Kh[(size_t)M_ROWS * E];
__device__ __half g_Vth[(size_t)B * E * S];
__device__ float  g_Sc[(size_t)B * S * S];
__device__ __half g_Ph[(size_t)B * S * S], g_Pl[(size_t)B * S * S];
__device__ __half g_AOh[(size_t)M_ROWS * E], g_AOl[(size_t)M_ROWS * E];

// ---------------------------------------------------------------------------
// PTX helpers (Ampere-compatible only: cp.async, ldmatrix, mma.sync)
// ---------------------------------------------------------------------------
__device__ __forceinline__ uint32_t smem_u32(const void* p) {
    uint32_t a;
    asm("{ .reg .u64 t; cvta.to.shared.u64 t, %1; cvt.u32.u64 %0, t; }" : "=r"(a) : "l"(p));
    return a;
}
#define SWZ(o) ((uint32_t)(o) ^ ((((uint32_t)(o)) >> 3) & 0x70))

#define CP_ASYNC16(dst, src) \
    asm volatile("cp.async.cg.shared.global [%0], [%1], 16;" :: "r"(dst), "l"(src) : "memory")
#define CP_COMMIT() asm volatile("cp.async.commit_group;" ::: "memory")
#define CP_WAIT0()  asm volatile("cp.async.wait_group 0;" ::: "memory")
#define CP_WAIT1()  asm volatile("cp.async.wait_group 1;" ::: "memory")

#define LDSM4(r0, r1, r2, r3, a) \
    asm volatile("ldmatrix.sync.aligned.m8n8.x4.shared.b16 {%0,%1,%2,%3}, [%4];" \
                 : "=r"(r0), "=r"(r1), "=r"(r2), "=r"(r3) : "r"(a))

#define MMAF16(c, a, b0, b1) \
    asm volatile("mma.sync.aligned.m16n8k16.row.col.f32.f16.f16.f32 " \
                 "{%0,%1,%2,%3},{%4,%5,%6,%7},{%8,%9},{%0,%1,%2,%3};" \
                 : "+f"((c)[0]), "+f"((c)[1]), "+f"((c)[2]), "+f"((c)[3]) \
                 : "r"((a)[0]), "r"((a)[1]), "r"((a)[2]), "r"((a)[3]), \
                   "r"(b0), "r"(b1))

// ---------------------------------------------------------------------------
// fp32 -> (fp16 hi, fp16 lo) conversions for the three inputs
// ---------------------------------------------------------------------------
__device__ __forceinline__ void cvt_body(const float* __restrict__ in,
                                         __half* __restrict__ h,
                                         __half* __restrict__ l)
{
    int i = (blockIdx.x * 256 + threadIdx.x) * 8;
    float4 a = *(const float4*)(in + i);
    float4 b2 = *(const float4*)(in + i + 4);
    float v[8] = {a.x, a.y, a.z, a.w, b2.x, b2.y, b2.z, b2.w};
    unsigned short hb[8], lb[8];
    #pragma unroll
    for (int j = 0; j < 8; j++) {
        __half hv = __float2half_rn(v[j]);
        float lo = v[j] - __half2float(hv);
        __half lv = __float2half_rn(lo);
        hb[j] = *(unsigned short*)&hv;
        lb[j] = *(unsigned short*)&lv;
    }
    *(uint4*)(h + i) = *(uint4*)hb;
    *(uint4*)(l + i) = *(uint4*)lb;
}

__global__ __launch_bounds__(256) void cvt3(
    const float* __restrict__ i0, const float* __restrict__ i1, const float* __restrict__ i2,
    __half* h0, __half* l0, __half* h1, __half* l1, __half* h2, __half* l2)
{
    const int z = blockIdx.y;
    const float* in = (z == 0) ? i0 : (z == 1) ? i1 : i2;
    __half* h = (z == 0) ? h0 : (z == 1) ? h1 : h2;
    __half* l = (z == 0) ? l0 : (z == 1) ? l1 : l2;
    cvt_body(in, h, l);
}

// Weights: hi only (B-operands never need a low part in the 2-term scheme)
__global__ __launch_bounds__(256) void cvtw(
    const float* __restrict__ i0, const float* __restrict__ i1,
    const float* __restrict__ i2, const float* __restrict__ i3,
    __half* h0, __half* h1, __half* h2, __half* h3)
{
    const int z = blockIdx.y;
    const float* in = (z == 0) ? i0 : (z == 1) ? i1 : (z == 2) ? i2 : i3;
    __half* h = (z == 0) ? h0 : (z == 1) ? h1 : (z == 2) ? h2 : h3;
    int i = (blockIdx.x * 256 + threadIdx.x) * 8;
    float4 a = *(const float4*)(in + i);
    float4 b2 = *(const float4*)(in + i + 4);
    float v[8] = {a.x, a.y, a.z, a.w, b2.x, b2.y, b2.z, b2.w};
    unsigned short hb[8];
    #pragma unroll
    for (int j = 0; j < 8; j++) {
        __half hv = __float2half_rn(v[j]);
        hb[j] = *(unsigned short*)&hv;
    }
    *(uint4*)(h + i) = *(uint4*)hb;
}

// ---------------------------------------------------------------------------
// Fused causal softmax: fp32 scores -> fp16-pair probabilities (zeros padded
// to the 128-multiple). Longest rows launched first.
// ---------------------------------------------------------------------------
__global__ __launch_bounds__(256) void softmax_pair(const float* __restrict__ Sc,
                                                    __half* __restrict__ Ph,
                                                    __half* __restrict__ Pl)
{
    const int row = blockIdx.x;
    const int b = row >> 11;
    const int q = (S - 1) - (row & (S - 1));   // descending: long rows first
    const float* ptr = Sc + (size_t)b * S * S + (size_t)q * S;
    const int len = q + 1;
    const int plen = ((q >> 7) + 1) << 7;
    const int tid = threadIdx.x;

    float vals[8];
    float m = -INFINITY;
    #pragma unroll
    for (int i = 0; i < 8; i++) {
        int k = tid + i * 256;
        vals[i] = (k < len) ? ptr[k] : -INFINITY;
        m = fmaxf(m, vals[i]);
    }
    __shared__ float red[256];
    red[tid] = m;
    __syncthreads();
    for (int s = 128; s > 0; s >>= 1) {
        if (tid < s) red[tid] = fmaxf(red[tid], red[tid + s]);
        __syncthreads();
    }
    m = red[0];
    __syncthreads();
    float sum = 0.f;
    #pragma unroll
    for (int i = 0; i < 8; i++) {
        int k = tid + i * 256;
        vals[i] = (k < len) ? __expf(vals[i] - m) : 0.f;
        sum += vals[i];
    }
    red[tid] = sum;
    __syncthreads();
    for (int s = 128; s > 0; s >>= 1) {
        if (tid < s) red[tid] += red[tid + s];
        __syncthreads();
    }
    const float inv = 1.0f / red[0];

    __half* ph = Ph + (size_t)b * S * S + (size_t)q * S;
    __half* pl = Pl + (size_t)b * S * S + (size_t)q * S;
    #pragma unroll
    for (int i = 0; i < 8; i++) {
        int k = tid + i * 256;
        if (k < plen) {
            float p = vals[i] * inv;
            __half h = __float2half_rn(p);
            ph[k] = h;
            pl[k] = __float2half_rn(p - __half2float(h));
        }
    }
}

// ---------------------------------------------------------------------------
// GEMM core: 128x256 fp32 tile of A[M,K]*Bop[N,K]^T, 2-term fp16 split:
//   C = Ah*Bh + Al*Bh  (A = hi+lo fp16, B = hi only)
// 8 warps of 64x64 (2x4), m16n8k16 via ldmatrix, 3-stage cp.async pipeline.
// A-fragment registers are REUSED between the hi and lo terms (halves the
// fragment register footprint vs R15; 32-MMA block hides the reload).
// ---------------------------------------------------------------------------
__device__ __forceinline__ void gemm_core(
    const __half* __restrict__ Ah, const __half* __restrict__ Al,
    const __half* __restrict__ Bh,
    int m0, int n0, int lda, int ldb, int NC, char* smem)
{
    const uint32_t smb = smem_u32(smem);
    const int tid = threadIdx.x;
    const int wid = tid >> 5, lane = tid & 31;
    const int warp_m = wid >> 2;        // 0..1 -> 64-row half
    const int warp_n = wid & 3;         // 0..3 -> 64-col quarter

    auto load_chunk = [&](int c, int s) {
        const int k0 = c * KB;
        const uint32_t stage = smb + s * STAGE_BYTES;
        // A tiles (128 rows): 4 iters each
        #pragma unroll
        for (int t = 0; t < 2; t++) {
            const __half* g = t ? Al : Ah;
            const uint32_t tb = stage + t * A_TILE;
            #pragma unroll
            for (int i = 0; i < 4; i++) {
                int sg = tid + 256 * i;
                int r = sg >> 3, sc = sg & 7;
                CP_ASYNC16(tb + SWZ(r * 128 + sc * 16),
                           g + (size_t)(m0 + r) * lda + k0 + sc * 8);
            }
        }
        // B tile (256 rows): 8 iters
        {
            const uint32_t tb = stage + 2 * A_TILE;
            #pragma unroll
            for (int i = 0; i < 8; i++) {
                int sg = tid + 256 * i;
                int r = sg >> 3, sc = sg & 7;
                CP_ASYNC16(tb + SWZ(r * 128 + sc * 16),
                           Bh + (size_t)(n0 + r) * ldb + k0 + sc * 8);
            }
        }
        CP_COMMIT();
    };

    float acc[4][8][4] = {};

    load_chunk(0, 0);
    if (NC > 1) load_chunk(1, 1);

    const int lg = lane >> 3, lr = lane & 7;
    const int rowA = warp_m * 64 + lr + (lg & 1) * 8;
    const int kA   = (lg >> 1) * 16;
    const int rowB = warp_n * 64 + lr + (lg >> 1) * 8;
    const int kBo  = (lg & 1) * 16;

    for (int c = 0; c < NC; c++) {
        if (c == NC - 1) { CP_WAIT0(); } else { CP_WAIT1(); }
        __syncthreads();
        if (c + 2 < NC) load_chunk(c + 2, (c + 2) % NSTAGE);

        const uint32_t stage = smb + (c % NSTAGE) * STAGE_BYTES;
        const uint32_t aH = stage, aL = stage + A_TILE;
        const uint32_t bH = stage + 2 * A_TILE;

        #pragma unroll
        for (int ks = 0; ks < 4; ks++) {
            const int koA = ks * 32 + kA;
            const int koB = ks * 32 + kBo;
            uint32_t af[4][4], bh[4][4];
            #pragma unroll
            for (int jp = 0; jp < 4; jp++) {
                uint32_t off = SWZ((rowB + jp * 16) * 128 + koB);
                LDSM4(bh[jp][0], bh[jp][1], bh[jp][2], bh[jp][3], bH + off);
            }
            // hi term
            #pragma unroll
            for (int i = 0; i < 4; i++) {
                uint32_t off = SWZ((rowA + i * 16) * 128 + koA);
                LDSM4(af[i][0], af[i][1], af[i][2], af[i][3], aH + off);
            }
            #pragma unroll
            for (int i = 0; i < 4; i++)
                #pragma unroll
                for (int j = 0; j < 8; j++) {
                    const int jp = j >> 1, h = (j & 1) * 2;
                    MMAF16(acc[i][j], af[i], bh[jp][h], bh[jp][h + 1]);
                }
            // lo term — reuse af registers (WAR covered by the MMA block)
            #pragma unroll
            for (int i = 0; i < 4; i++) {
                uint32_t off = SWZ((rowA + i * 16) * 128 + koA);
                LDSM4(af[i][0], af[i][1], af[i][2], af[i][3], aL + off);
            }
            #pragma unroll
            for (int i = 0; i < 4; i++)
                #pragma unroll
                for (int j = 0; j < 8; j++) {
                    const int jp = j >> 1, h = (j & 1) * 2;
                    MMAF16(acc[i][j], af[i], bh[jp][h], bh[jp][h + 1]);
                }
        }
        // no trailing sync: next iteration's leading sync provides the barrier
    }
    __syncthreads();

    // regs -> smem ep[128][EPIT]
    float* ep = (float*)smem;
    const int erow = lane >> 2;
    const int ecol = (lane & 3) * 2;
    #pragma unroll
    for (int i = 0; i < 4; i++) {
        int rbase = warp_m * 64 + i * 16 + erow;
        #pragma unroll
        for (int j = 0; j < 8; j++) {
            int cc = warp_n * 64 + j * 8 + ecol;
            ep[rbase * EPIT + cc]           = acc[i][j][0];
            ep[rbase * EPIT + cc + 1]       = acc[i][j][1];
            ep[(rbase + 8) * EPIT + cc]     = acc[i][j][2];
            ep[(rbase + 8) * EPIT + cc + 1] = acc[i][j][3];
        }
    }
    __syncthreads();
}

// fp16-pair store: ep[128][EPIT] (+bias)*scale -> hi/lo arrays (128x256 tile)
__device__ __forceinline__ void store_pair(
    const float* ep, const float* bias, float scale,
    __half* oH, __half* oL, int m0, int n0, int ldc)
{
    const int tid = threadIdx.x;
    #pragma unroll
    for (int i = 0; i < 16; i++) {
        int idx = tid + NTHR * i;
        int r = idx >> 5, c8 = (idx & 31) * 8;
        unsigned short hb[8], lb[8];
        #pragma unroll
        for (int j = 0; j < 8; j++) {
            float v = ep[r * EPIT + c8 + j];
            if (bias) v = (v + bias[n0 + c8 + j]) * scale;
            __half hv = __float2half_rn(v);
            float lo = v - __half2float(hv);
            __half lv = __float2half_rn(lo);
            hb[j] = *(unsigned short*)&hv;
            lb[j] = *(unsigned short*)&lv;
        }
        size_t off = (size_t)(m0 + r) * ldc + n0 + c8;
        *(uint4*)(oH + off) = *(uint4*)hb;
        *(uint4*)(oL + off) = *(uint4*)lb;
    }
}

// fp16 hi-only store: ep + bias -> single array (128x256 tile)
__device__ __forceinline__ void store_hi(
    const float* ep, const float* bias,
    __half* oH, int m0, int n0, int ldc)
{
    const int tid = threadIdx.x;
    #pragma unroll
    for (int i = 0; i < 16; i++) {
        int idx = tid + NTHR * i;
        int r = idx >> 5, c8 = (idx & 31) * 8;
        unsigned short hb[8];
        #pragma unroll
        for (int j = 0; j < 8; j++) {
            float v = ep[r * EPIT + c8 + j] + bias[n0 + c8 + j];
            __half hv = __float2half_rn(v);
            hb[j] = *(unsigned short*)&hv;
        }
        *(uint4*)(oH + (size_t)(m0 + r) * ldc + n0 + c8) = *(uint4*)hb;
    }
}

// ---------------------------------------------------------------------------
// Fused Q/K/V projection: blockIdx.z selects tensor. Q folds the 1/32 scale
// (hi/lo out); K hi-only; V transposed hi-only [b][e][s].
// ---------------------------------------------------------------------------
__global__ __launch_bounds__(NTHR, 1) void proj_qkv(
    const __half* __restrict__ qh, const __half* __restrict__ ql,
    const __half* __restrict__ kh, const __half* __restrict__ kl,
    const __half* __restrict__ vh, const __half* __restrict__ vl,
    const __half* __restrict__ wqh, const __half* __restrict__ wkh,
    const __half* __restrict__ wvh,
    const float* __restrict__ bq, const float* __restrict__ bk, const float* __restrict__ bv,
    __half* Qh, __half* Ql, __half* Kh, __half* Vth)
{
    extern __shared__ __align__(1024) char smem[];
    const int z = blockIdx.z;
    const int m0 = blockIdx.y * TM, n0 = blockIdx.x * TN;

    const __half *Ah, *Al, *Bh;
    const float* bias;
    if (z == 0)      { Ah = qh; Al = ql; Bh = wqh; bias = bq; }
    else if (z == 1) { Ah = kh; Al = kl; Bh = wkh; bias = bk; }
    else             { Ah = vh; Al = vl; Bh = wvh; bias = bv; }

    gemm_core(Ah, Al, Bh, m0, n0, E, E, E / KB, smem);
    const float* ep = (const float*)smem;
    const int tid = threadIdx.x;

    if (z == 0) {
        store_pair(ep, bias, 0.03125f, Qh, Ql, m0, n0, E);
    } else if (z == 1) {
        store_hi(ep, bias, Kh, m0, n0, E);
    } else {
        // transposed hi-only store: V[m0+r][n0+col] -> Vt[b][n0+col][s0+r]
        const int bb = m0 >> 11;
        const int s0 = m0 & (S - 1);
        const int col = tid;              // 0..255
        const float bcol = bias[n0 + col];
        __half* oH = Vth + ((size_t)bb * E + n0 + col) * S + s0;
        #pragma unroll
        for (int r0 = 0; r0 < 128; r0 += 8) {
            unsigned short hb[8];
            #pragma unroll
            for (int k = 0; k < 8; k++) {
                float v = ep[(r0 + k) * EPIT + col] + bcol;
                __half hv = __float2half_rn(v);
                hb[k] = *(unsigned short*)&hv;
            }
            *(uint4*)(oH + r0) = *(uint4*)hb;
        }
    }
}

// ---------------------------------------------------------------------------
// Scores: compact triangular grid over 128x256 tiles — tile (mi,ni) has work
// iff ni <= mi/2. 72 tiles per batch.
// ---------------------------------------------------------------------------
__global__ __launch_bounds__(NTHR, 1) void scores_mma(
    const __half* __restrict__ Qh, const __half* __restrict__ Ql,
    const __half* __restrict__ Kh, float* __restrict__ Sc)
{
    extern __shared__ __align__(1024) char smem[];
    const int b = blockIdx.z;
    int t = blockIdx.x;
    int mi = 0;
    #pragma unroll
    for (int m = 0; m < 16; m++) {
        int cnt = m / 2 + 1;
        if (t < cnt) { mi = m; break; }
        t -= cnt;
    }
    const int ni = t;
    const int m0 = mi * TM, n0 = ni * TN;

    const size_t boff = (size_t)b * S * E;
    gemm_core(Qh + boff, Ql + boff, Kh + boff, m0, n0, E, E, E / KB, smem);
    const float* ep = (const float*)smem;
    float* oF = Sc + (size_t)b * S * S;
    const int tid = threadIdx.x;
    #pragma unroll
    for (int i = 0; i < 32; i++) {
        int idx = tid + NTHR * i;
        int r = idx >> 6, c4 = (idx & 63) * 4;
        float4 o;
        o.x = ep[r * EPIT + c4 + 0];
        o.y = ep[r * EPIT + c4 + 1];
        o.z = ep[r * EPIT + c4 + 2];
        o.w = ep[r * EPIT + c4 + 3];
        *(float4*)&oF[(size_t)(m0 + r) * S + n0 + c4] = o;
    }
}

// ---------------------------------------------------------------------------
// attn_out = P @ V (K clipped at diagonal tile), fp16-pair out.
// Longest m-tiles first.
// ---------------------------------------------------------------------------
__global__ __launch_bounds__(NTHR, 1) void attnv_mma(
    const __half* __restrict__ Ph, const __half* __restrict__ Pl,
    const __half* __restrict__ Vth,
    __half* AOh, __half* AOl)
{
    extern __shared__ __align__(1024) char smem[];
    const int b = blockIdx.z;
    const int mi = (gridDim.y - 1) - blockIdx.y;   // longest first
    const int m0 = mi * TM, n0 = blockIdx.x * TN;
    const size_t poff = (size_t)b * S * S, voff = (size_t)b * E * S;

    gemm_core(Ph + poff, Pl + poff, Vth + voff,
              m0, n0, S, S, (m0 + TM) / KB, smem);
    const float* ep = (const float*)smem;
    store_pair(ep, nullptr, 1.0f, AOh + (size_t)b * S * E, AOl + (size_t)b * S * E,
               m0, n0, E);
}

// ---------------------------------------------------------------------------
// Output projection: out = AO @ Wo^T + bo (fp32)
// ---------------------------------------------------------------------------
__global__ __launch_bounds__(NTHR, 1) void outproj_mma(
    const __half* __restrict__ AOh, const __half* __restrict__ AOl,
    const __half* __restrict__ woh,
    const float* __restrict__ bo, float* __restrict__ out)
{
    extern __shared__ __align__(1024) char smem[];
    const int m0 = blockIdx.y * TM, n0 = blockIdx.x * TN;
    gemm_core(AOh, AOl, woh, m0, n0, E, E, E / KB, smem);
    const float* ep = (const float*)smem;
    const int tid = threadIdx.x;
    #pragma unroll
    for (int i = 0; i < 32; i++) {
        int idx = tid + NTHR * i;
        int r = idx >> 6, c4 = (idx & 63) * 4;
        float4 bv = *(const float4*)&bo[n0 + c4];
        float4 o;
        o.x = ep[r * EPIT + c4 + 0] + bv.x;
        o.y = ep[r * EPIT + c4 + 1] + bv.y;
        o.z = ep[r * EPIT + c4 + 2] + bv.z;
        o.w = ep[r * EPIT + c4 + 3] + bv.w;
        *(float4*)&out[(size_t)(m0 + r) * E + n0 + c4] = o;
    }
}

// ---------------------------------------------------------------------------
// Host launcher
// ---------------------------------------------------------------------------
extern "C" void kernel_launch(void* const* d_in, const int* in_sizes, int n_in,
                              void* d_out, int out_size)
{
    const float* query = (const float*)d_in[0];
    const float* key_  = (const float*)d_in[1];
    const float* value = (const float*)d_in[2];
    const float* Wq = (const float*)d_in[4];
    const float* bq = (const float*)d_in[5];
    const float* Wk = (const float*)d_in[6];
    const float* bk = (const float*)d_in[7];
    const float* Wv = (const float*)d_in[8];
    const float* bv = (const float*)d_in[9];
    const float* Wo = (const float*)d_in[10];
    const float* bo = (const float*)d_in[11];
    float* out = (float*)d_out;

    #define SYM(p, s) void* p; cudaGetSymbolAddress(&p, s)
    SYM(qh, g_qh); SYM(ql, g_ql); SYM(kh, g_kh); SYM(kl, g_kl); SYM(vh, g_vh); SYM(vl, g_vl);
    SYM(wqh, g_wqh); SYM(wkh, g_wkh); SYM(wvh, g_wvh); SYM(woh, g_woh);
    SYM(Qh, g_Qh); SYM(Ql, g_Ql); SYM(Kh, g_Kh); SYM(Vth, g_Vth);
    SYM(Sc, g_Sc); SYM(Ph, g_Ph); SYM(Pl, g_Pl); SYM(AOh, g_AOh); SYM(AOl, g_AOl);
    #undef SYM
    typedef __half hf;

    cudaFuncSetAttribute((const void*)proj_qkv,    cudaFuncAttributeMaxDynamicSharedMemorySize, SMEM_SZ);
    cudaFuncSetAttribute((const void*)scores_mma,  cudaFuncAttributeMaxDynamicSharedMemorySize, SMEM_SZ);
    cudaFuncSetAttribute((const void*)attnv_mma,   cudaFuncAttributeMaxDynamicSharedMemorySize, SMEM_SZ);
    cudaFuncSetAttribute((const void*)outproj_mma, cudaFuncAttributeMaxDynamicSharedMemorySize, SMEM_SZ);

    // 1) fp32 -> fp16 conversions (inputs hi/lo; weights hi-only)
    const int nIn = M_ROWS * E, nW = E * E;
    cvt3<<<dim3(nIn / 2048, 3), 256>>>(query, key_, value,
        (hf*)qh, (hf*)ql, (hf*)kh, (hf*)kl, (hf*)vh, (hf*)vl);
    cvtw<<<dim3(nW / 2048, 4), 256>>>(Wq, Wk, Wv, Wo,
        (hf*)wqh, (hf*)wkh, (hf*)wvh, (hf*)woh);

    // 2) fused Q/K/V projections (Q scaled by 1/32 hi/lo; K hi; V transposed hi)
    proj_qkv<<<dim3(E / TN, M_ROWS / TM, 3), NTHR, SMEM_SZ>>>(
        (hf*)qh, (hf*)ql, (hf*)kh, (hf*)kl, (hf*)vh, (hf*)vl,
        (hf*)wqh, (hf*)wkh, (hf*)wvh,
        bq, bk, bv,
        (hf*)Qh, (hf*)Ql, (hf*)Kh, (hf*)Vth);

    // 3) scores — compact triangular grid: 72 tiles per batch
    scores_mma<<<dim3(72, 1, B), NTHR, SMEM_SZ>>>(
        (hf*)Qh, (hf*)Ql, (hf*)Kh, (float*)Sc);

    // 4) fused softmax -> fp16-pair P (longest rows first)
    softmax_pair<<<B * S, 256>>>((const float*)Sc, (hf*)Ph, (hf*)Pl);

    // 5) attn_out = P @ V (longest m-tiles first)
    attnv_mma<<<dim3(E / TN, S / TM, B), NTHR, SMEM_SZ>>>(
        (hf*)Ph, (hf*)Pl, (hf*)Vth, (hf*)AOh, (hf*)AOl);

    // 6) output projection -> d_out
    outproj_mma<<<dim3(E / TN, M_ROWS / TM, 1), NTHR, SMEM_SZ>>>(
        (hf*)AOh, (hf*)AOl, (hf*)woh, bo, out);
}

// round 17
// speedup vs baseline: 1.5665x; 1.5665x over previous
#include <cuda_runtime.h>
#include <cuda_fp16.h>
#include <cstdint>
#include <math.h>

// ---------------------------------------------------------------------------
// Problem constants
// ---------------------------------------------------------------------------
constexpr int B = 4;
constexpr int S = 2048;
constexpr int E = 1024;
constexpr int M_ROWS = B * S;   // 8192

constexpr int NTHR = 256;
constexpr int KB = 64;

// core32 (64x32 warp tile, CTA 128x128)  — proj/attnv/outproj
constexpr int TM = 128, TN = 128;
constexpr int TILE32 = 128 * 128;                 // 16KB
constexpr int STAGE32 = 3 * TILE32;               // Ah, Al, Bh = 48KB
constexpr int NSTAGE = 3;
constexpr int SMEM32 = NSTAGE * STAGE32;          // 144KB
constexpr int EPIT32 = 132;

// core64 (64x64 warp tile, CTA 128x256) — scores only
constexpr int TN2 = 256;
constexpr int A_TILE = 128 * 128;                 // 16KB
constexpr int B_TILE = 256 * 128;                 // 32KB
constexpr int STAGE64 = 2 * A_TILE + B_TILE;      // 64KB
constexpr int SMEM64 = NSTAGE * STAGE64;          // 192KB
constexpr int EPIT64 = 260;

// ---------------------------------------------------------------------------
// Scratch (device globals — no allocations allowed)
// ---------------------------------------------------------------------------
__device__ __half g_qh[(size_t)M_ROWS * E], g_ql[(size_t)M_ROWS * E];
__device__ __half g_kh[(size_t)M_ROWS * E], g_kl[(size_t)M_ROWS * E];
__device__ __half g_vh[(size_t)M_ROWS * E], g_vl[(size_t)M_ROWS * E];
__device__ __half g_wqh[(size_t)E * E];
__device__ __half g_wkh[(size_t)E * E];
__device__ __half g_wvh[(size_t)E * E];
__device__ __half g_woh[(size_t)E * E];
__device__ __half g_Qh[(size_t)M_ROWS * E], g_Ql[(size_t)M_ROWS * E];
__device__ __half g_Kh[(size_t)M_ROWS * E];
__device__ __half g_Vth[(size_t)B * E * S];
__device__ float  g_Sc[(size_t)B * S * S];
__device__ __half g_Ph[(size_t)B * S * S], g_Pl[(size_t)B * S * S];
__device__ __half g_AOh[(size_t)M_ROWS * E], g_AOl[(size_t)M_ROWS * E];

// ---------------------------------------------------------------------------
// PTX helpers
// ---------------------------------------------------------------------------
__device__ __forceinline__ uint32_t smem_u32(const void* p) {
    uint32_t a;
    asm("{ .reg .u64 t; cvta.to.shared.u64 t, %1; cvt.u32.u64 %0, t; }" : "=r"(a) : "l"(p));
    return a;
}
#define SWZ(o) ((uint32_t)(o) ^ ((((uint32_t)(o)) >> 3) & 0x70))

#define CP_ASYNC16(dst, src) \
    asm volatile("cp.async.cg.shared.global [%0], [%1], 16;" :: "r"(dst), "l"(src) : "memory")
#define CP_COMMIT() asm volatile("cp.async.commit_group;" ::: "memory")
#define CP_WAIT0()  asm volatile("cp.async.wait_group 0;" ::: "memory")
#define CP_WAIT1()  asm volatile("cp.async.wait_group 1;" ::: "memory")

#define LDSM4(r0, r1, r2, r3, a) \
    asm volatile("ldmatrix.sync.aligned.m8n8.x4.shared.b16 {%0,%1,%2,%3}, [%4];" \
                 : "=r"(r0), "=r"(r1), "=r"(r2), "=r"(r3) : "r"(a))

#define MMAF16(c, a, b0, b1) \
    asm volatile("mma.sync.aligned.m16n8k16.row.col.f32.f16.f16.f32 " \
                 "{%0,%1,%2,%3},{%4,%5,%6,%7},{%8,%9},{%0,%1,%2,%3};" \
                 : "+f"((c)[0]), "+f"((c)[1]), "+f"((c)[2]), "+f"((c)[3]) \
                 : "r"((a)[0]), "r"((a)[1]), "r"((a)[2]), "r"((a)[3]), \
                   "r"(b0), "r"(b1))

// ---------------------------------------------------------------------------
// fp32 -> (fp16 hi, fp16 lo) conversions
// ---------------------------------------------------------------------------
__device__ __forceinline__ void cvt_body(const float* __restrict__ in,
                                         __half* __restrict__ h,
                                         __half* __restrict__ l)
{
    int i = (blockIdx.x * 256 + threadIdx.x) * 8;
    float4 a = *(const float4*)(in + i);
    float4 b2 = *(const float4*)(in + i + 4);
    float v[8] = {a.x, a.y, a.z, a.w, b2.x, b2.y, b2.z, b2.w};
    unsigned short hb[8], lb[8];
    #pragma unroll
    for (int j = 0; j < 8; j++) {
        __half hv = __float2half_rn(v[j]);
        float lo = v[j] - __half2float(hv);
        __half lv = __float2half_rn(lo);
        hb[j] = *(unsigned short*)&hv;
        lb[j] = *(unsigned short*)&lv;
    }
    *(uint4*)(h + i) = *(uint4*)hb;
    *(uint4*)(l + i) = *(uint4*)lb;
}

__global__ __launch_bounds__(256) void cvt3(
    const float* __restrict__ i0, const float* __restrict__ i1, const float* __restrict__ i2,
    __half* h0, __half* l0, __half* h1, __half* l1, __half* h2, __half* l2)
{
    const int z = blockIdx.y;
    const float* in = (z == 0) ? i0 : (z == 1) ? i1 : i2;
    __half* h = (z == 0) ? h0 : (z == 1) ? h1 : h2;
    __half* l = (z == 0) ? l0 : (z == 1) ? l1 : l2;
    cvt_body(in, h, l);
}

__global__ __launch_bounds__(256) void cvtw(
    const float* __restrict__ i0, const float* __restrict__ i1,
    const float* __restrict__ i2, const float* __restrict__ i3,
    __half* h0, __half* h1, __half* h2, __half* h3)
{
    const int z = blockIdx.y;
    const float* in = (z == 0) ? i0 : (z == 1) ? i1 : (z == 2) ? i2 : i3;
    __half* h = (z == 0) ? h0 : (z == 1) ? h1 : (z == 2) ? h2 : h3;
    int i = (blockIdx.x * 256 + threadIdx.x) * 8;
    float4 a = *(const float4*)(in + i);
    float4 b2 = *(const float4*)(in + i + 4);
    float v[8] = {a.x, a.y, a.z, a.w, b2.x, b2.y, b2.z, b2.w};
    unsigned short hb[8];
    #pragma unroll
    for (int j = 0; j < 8; j++) {
        __half hv = __float2half_rn(v[j]);
        hb[j] = *(unsigned short*)&hv;
    }
    *(uint4*)(h + i) = *(uint4*)hb;
}

// ---------------------------------------------------------------------------
// Fused causal softmax (longest rows first)
// ---------------------------------------------------------------------------
__global__ __launch_bounds__(256) void softmax_pair(const float* __restrict__ Sc,
                                                    __half* __restrict__ Ph,
                                                    __half* __restrict__ Pl)
{
    const int row = blockIdx.x;
    const int b = row >> 11;
    const int q = (S - 1) - (row & (S - 1));
    const float* ptr = Sc + (size_t)b * S * S + (size_t)q * S;
    const int len = q + 1;
    const int plen = ((q >> 7) + 1) << 7;
    const int tid = threadIdx.x;

    float vals[8];
    float m = -INFINITY;
    #pragma unroll
    for (int i = 0; i < 8; i++) {
        int k = tid + i * 256;
        vals[i] = (k < len) ? ptr[k] : -INFINITY;
        m = fmaxf(m, vals[i]);
    }
    __shared__ float red[256];
    red[tid] = m;
    __syncthreads();
    for (int s = 128; s > 0; s >>= 1) {
        if (tid < s) red[tid] = fmaxf(red[tid], red[tid + s]);
        __syncthreads();
    }
    m = red[0];
    __syncthreads();
    float sum = 0.f;
    #pragma unroll
    for (int i = 0; i < 8; i++) {
        int k = tid + i * 256;
        vals[i] = (k < len) ? __expf(vals[i] - m) : 0.f;
        sum += vals[i];
    }
    red[tid] = sum;
    __syncthreads();
    for (int s = 128; s > 0; s >>= 1) {
        if (tid < s) red[tid] += red[tid + s];
        __syncthreads();
    }
    const float inv = 1.0f / red[0];

    __half* ph = Ph + (size_t)b * S * S + (size_t)q * S;
    __half* pl = Pl + (size_t)b * S * S + (size_t)q * S;
    #pragma unroll
    for (int i = 0; i < 8; i++) {
        int k = tid + i * 256;
        if (k < plen) {
            float p = vals[i] * inv;
            __half h = __float2half_rn(p);
            ph[k] = h;
            pl[k] = __float2half_rn(p - __half2float(h));
        }
    }
}

// ---------------------------------------------------------------------------
// core32: 128x128 tile, 8 warps of 64x32 (R14-proven)
// ---------------------------------------------------------------------------
__device__ __forceinline__ void gemm_core32(
    const __half* __restrict__ Ah, const __half* __restrict__ Al,
    const __half* __restrict__ Bh,
    int m0, int n0, int lda, int ldb, int NC, char* smem)
{
    const uint32_t smb = smem_u32(smem);
    const int tid = threadIdx.x;
    const int wid = tid >> 5, lane = tid & 31;
    const int warp_m = wid >> 2;
    const int warp_n = wid & 3;

    auto load_chunk = [&](int c, int s) {
        const int k0 = c * KB;
        const uint32_t stage = smb + s * STAGE32;
        const __half* gp[3] = {Ah, Al, Bh};
        #pragma unroll
        for (int t = 0; t < 3; t++) {
            const __half* g = gp[t];
            const int r0 = (t < 2) ? m0 : n0;
            const int ld = (t < 2) ? lda : ldb;
            const uint32_t tbase = stage + t * TILE32;
            #pragma unroll
            for (int i = 0; i < 4; i++) {
                int sg = tid + 256 * i;
                int r = sg >> 3, sc = sg & 7;
                CP_ASYNC16(tbase + SWZ(r * 128 + sc * 16),
                           g + (size_t)(r0 + r) * ld + k0 + sc * 8);
            }
        }
        CP_COMMIT();
    };

    float acc[4][4][4] = {};

    load_chunk(0, 0);
    if (NC > 1) load_chunk(1, 1);

    const int lg = lane >> 3, lr = lane & 7;
    const int rowA = warp_m * 64 + lr + (lg & 1) * 8;
    const int kA   = (lg >> 1) * 16;
    const int rowB = warp_n * 32 + lr + (lg >> 1) * 8;
    const int kBo  = (lg & 1) * 16;

    uint32_t ah[2][4][4], al[2][4][4], bh[2][2][4];

    for (int c = 0; c < NC; c++) {
        if (c == NC - 1) { CP_WAIT0(); } else { CP_WAIT1(); }
        __syncthreads();
        if (c + 2 < NC) load_chunk(c + 2, (c + 2) % NSTAGE);

        const uint32_t stage = smb + (c % NSTAGE) * STAGE32;
        const uint32_t aH = stage, aL = stage + TILE32;
        const uint32_t bH = stage + 2 * TILE32;

        auto load_frags = [&](int ks, int bu) {
            const int koA = ks * 32 + kA;
            const int koB = ks * 32 + kBo;
            #pragma unroll
            for (int i = 0; i < 4; i++) {
                uint32_t off = SWZ((rowA + i * 16) * 128 + koA);
                LDSM4(ah[bu][i][0], ah[bu][i][1], ah[bu][i][2], ah[bu][i][3], aH + off);
                LDSM4(al[bu][i][0], al[bu][i][1], al[bu][i][2], al[bu][i][3], aL + off);
            }
            #pragma unroll
            for (int p = 0; p < 2; p++) {
                uint32_t off = SWZ((rowB + p * 16) * 128 + koB);
                LDSM4(bh[bu][p][0], bh[bu][p][1], bh[bu][p][2], bh[bu][p][3], bH + off);
            }
        };

        load_frags(0, 0);
        #pragma unroll
        for (int ks = 0; ks < 4; ks++) {
            const int cur = ks & 1, nxt = cur ^ 1;
            if (ks < 3) load_frags(ks + 1, nxt);
            #pragma unroll
            for (int i = 0; i < 4; i++)
                #pragma unroll
                for (int j = 0; j < 4; j++) {
                    const int p = j >> 1, h = (j & 1) * 2;
                    MMAF16(acc[i][j], ah[cur][i], bh[cur][p][h], bh[cur][p][h + 1]);
                }
            #pragma unroll
            for (int i = 0; i < 4; i++)
                #pragma unroll
                for (int j = 0; j < 4; j++) {
                    const int p = j >> 1, h = (j & 1) * 2;
                    MMAF16(acc[i][j], al[cur][i], bh[cur][p][h], bh[cur][p][h + 1]);
                }
        }
    }
    __syncthreads();

    float* ep = (float*)smem;
    const int erow = lane >> 2;
    const int ecol = (lane & 3) * 2;
    #pragma unroll
    for (int i = 0; i < 4; i++) {
        int rbase = warp_m * 64 + i * 16 + erow;
        #pragma unroll
        for (int j = 0; j < 4; j++) {
            int cc = warp_n * 32 + j * 8 + ecol;
            ep[rbase * EPIT32 + cc]           = acc[i][j][0];
            ep[rbase * EPIT32 + cc + 1]       = acc[i][j][1];
            ep[(rbase + 8) * EPIT32 + cc]     = acc[i][j][2];
            ep[(rbase + 8) * EPIT32 + cc + 1] = acc[i][j][3];
        }
    }
    __syncthreads();
}

// fp16-pair store for 128x128 tiles (EPIT32)
__device__ __forceinline__ void store_pair32(
    const float* ep, const float* bias, float scale,
    __half* oH, __half* oL, int m0, int n0, int ldc)
{
    const int tid = threadIdx.x;
    #pragma unroll
    for (int i = 0; i < 8; i++) {
        int idx = tid + NTHR * i;
        int r = idx >> 4, c8 = (idx & 15) * 8;
        unsigned short hb[8], lb[8];
        #pragma unroll
        for (int j = 0; j < 8; j++) {
            float v = ep[r * EPIT32 + c8 + j];
            if (bias) v = (v + bias[n0 + c8 + j]) * scale;
            __half hv = __float2half_rn(v);
            float lo = v - __half2float(hv);
            __half lv = __float2half_rn(lo);
            hb[j] = *(unsigned short*)&hv;
            lb[j] = *(unsigned short*)&lv;
        }
        size_t off = (size_t)(m0 + r) * ldc + n0 + c8;
        *(uint4*)(oH + off) = *(uint4*)hb;
        *(uint4*)(oL + off) = *(uint4*)lb;
    }
}

__device__ __forceinline__ void store_hi32(
    const float* ep, const float* bias,
    __half* oH, int m0, int n0, int ldc)
{
    const int tid = threadIdx.x;
    #pragma unroll
    for (int i = 0; i < 8; i++) {
        int idx = tid + NTHR * i;
        int r = idx >> 4, c8 = (idx & 15) * 8;
        unsigned short hb[8];
        #pragma unroll
        for (int j = 0; j < 8; j++) {
            float v = ep[r * EPIT32 + c8 + j] + bias[n0 + c8 + j];
            __half hv = __float2half_rn(v);
            hb[j] = *(unsigned short*)&hv;
        }
        *(uint4*)(oH + (size_t)(m0 + r) * ldc + n0 + c8) = *(uint4*)hb;
    }
}

// ---------------------------------------------------------------------------
// core64: 128x256 tile, 8 warps of 64x64 (R15-proven) — used by scores only
// ---------------------------------------------------------------------------
__device__ __forceinline__ void gemm_core64(
    const __half* __restrict__ Ah, const __half* __restrict__ Al,
    const __half* __restrict__ Bh,
    int m0, int n0, int lda, int ldb, int NC, char* smem)
{
    const uint32_t smb = smem_u32(smem);
    const int tid = threadIdx.x;
    const int wid = tid >> 5, lane = tid & 31;
    const int warp_m = wid >> 2;
    const int warp_n = wid & 3;

    auto load_chunk = [&](int c, int s) {
        const int k0 = c * KB;
        const uint32_t stage = smb + s * STAGE64;
        #pragma unroll
        for (int t = 0; t < 2; t++) {
            const __half* g = t ? Al : Ah;
            const uint32_t tb = stage + t * A_TILE;
            #pragma unroll
            for (int i = 0; i < 4; i++) {
                int sg = tid + 256 * i;
                int r = sg >> 3, sc = sg & 7;
                CP_ASYNC16(tb + SWZ(r * 128 + sc * 16),
                           g + (size_t)(m0 + r) * lda + k0 + sc * 8);
            }
        }
        {
            const uint32_t tb = stage + 2 * A_TILE;
            #pragma unroll
            for (int i = 0; i < 8; i++) {
                int sg = tid + 256 * i;
                int r = sg >> 3, sc = sg & 7;
                CP_ASYNC16(tb + SWZ(r * 128 + sc * 16),
                           Bh + (size_t)(n0 + r) * ldb + k0 + sc * 8);
            }
        }
        CP_COMMIT();
    };

    float acc[4][8][4] = {};

    load_chunk(0, 0);
    if (NC > 1) load_chunk(1, 1);

    const int lg = lane >> 3, lr = lane & 7;
    const int rowA = warp_m * 64 + lr + (lg & 1) * 8;
    const int kA   = (lg >> 1) * 16;
    const int rowB = warp_n * 64 + lr + (lg >> 1) * 8;
    const int kBo  = (lg & 1) * 16;

    for (int c = 0; c < NC; c++) {
        if (c == NC - 1) { CP_WAIT0(); } else { CP_WAIT1(); }
        __syncthreads();
        if (c + 2 < NC) load_chunk(c + 2, (c + 2) % NSTAGE);

        const uint32_t stage = smb + (c % NSTAGE) * STAGE64;
        const uint32_t aH = stage, aL = stage + A_TILE;
        const uint32_t bH = stage + 2 * A_TILE;

        #pragma unroll
        for (int ks = 0; ks < 4; ks++) {
            const int koA = ks * 32 + kA;
            const int koB = ks * 32 + kBo;
            uint32_t ah[4][4], al[4][4], bh[4][4];
            #pragma unroll
            for (int i = 0; i < 4; i++) {
                uint32_t off = SWZ((rowA + i * 16) * 128 + koA);
                LDSM4(ah[i][0], ah[i][1], ah[i][2], ah[i][3], aH + off);
                LDSM4(al[i][0], al[i][1], al[i][2], al[i][3], aL + off);
            }
            #pragma unroll
            for (int jp = 0; jp < 4; jp++) {
                uint32_t off = SWZ((rowB + jp * 16) * 128 + koB);
                LDSM4(bh[jp][0], bh[jp][1], bh[jp][2], bh[jp][3], bH + off);
            }
            #pragma unroll
            for (int i = 0; i < 4; i++)
                #pragma unroll
                for (int j = 0; j < 8; j++) {
                    const int jp = j >> 1, h = (j & 1) * 2;
                    MMAF16(acc[i][j], ah[i], bh[jp][h], bh[jp][h + 1]);
                }
            #pragma unroll
            for (int i = 0; i < 4; i++)
                #pragma unroll
                for (int j = 0; j < 8; j++) {
                    const int jp = j >> 1, h = (j & 1) * 2;
                    MMAF16(acc[i][j], al[i], bh[jp][h], bh[jp][h + 1]);
                }
        }
    }
    __syncthreads();

    float* ep = (float*)smem;
    const int erow = lane >> 2;
    const int ecol = (lane & 3) * 2;
    #pragma unroll
    for (int i = 0; i < 4; i++) {
        int rbase = warp_m * 64 + i * 16 + erow;
        #pragma unroll
        for (int j = 0; j < 8; j++) {
            int cc = warp_n * 64 + j * 8 + ecol;
            ep[rbase * EPIT64 + cc]           = acc[i][j][0];
            ep[rbase * EPIT64 + cc + 1]       = acc[i][j][1];
            ep[(rbase + 8) * EPIT64 + cc]     = acc[i][j][2];
            ep[(rbase + 8) * EPIT64 + cc + 1] = acc[i][j][3];
        }
    }
    __syncthreads();
}

// ---------------------------------------------------------------------------
// Fused Q/K/V projection (core32)
// ---------------------------------------------------------------------------
__global__ __launch_bounds__(NTHR, 1) void proj_qkv(
    const __half* __restrict__ qh, const __half* __restrict__ ql,
    const __half* __restrict__ kh, const __half* __restrict__ kl,
    const __half* __restrict__ vh, const __half* __restrict__ vl,
    const __half* __restrict__ wqh, const __half* __restrict__ wkh,
    const __half* __restrict__ wvh,
    const float* __restrict__ bq, const float* __restrict__ bk, const float* __restrict__ bv,
    __half* Qh, __half* Ql, __half* Kh, __half* Vth)
{
    extern __shared__ __align__(1024) char smem[];
    const int z = blockIdx.z;
    const int m0 = blockIdx.y * TM, n0 = blockIdx.x * TN;

    const __half *Ah, *Al, *Bh;
    const float* bias;
    if (z == 0)      { Ah = qh; Al = ql; Bh = wqh; bias = bq; }
    else if (z == 1) { Ah = kh; Al = kl; Bh = wkh; bias = bk; }
    else             { Ah = vh; Al = vl; Bh = wvh; bias = bv; }

    gemm_core32(Ah, Al, Bh, m0, n0, E, E, E / KB, smem);
    const float* ep = (const float*)smem;
    const int tid = threadIdx.x;

    if (z == 0) {
        store_pair32(ep, bias, 0.03125f, Qh, Ql, m0, n0, E);
    } else if (z == 1) {
        store_hi32(ep, bias, Kh, m0, n0, E);
    } else {
        const int bb = m0 >> 11;
        const int s0 = m0 & (S - 1);
        const int col = tid & 127, half_sel = tid >> 7;
        const float bcol = bias[n0 + col];
        __half* oH = Vth + ((size_t)bb * E + n0 + col) * S + s0 + half_sel * 64;
        #pragma unroll
        for (int r0 = 0; r0 < 64; r0 += 8) {
            unsigned short hb[8];
            #pragma unroll
            for (int k = 0; k < 8; k++) {
                float v = ep[(half_sel * 64 + r0 + k) * EPIT32 + col] + bcol;
                __half hv = __float2half_rn(v);
                hb[k] = *(unsigned short*)&hv;
            }
            *(uint4*)(oH + r0) = *(uint4*)hb;
        }
    }
}

// ---------------------------------------------------------------------------
// Scores (core64): compact triangular grid over 128x256 tiles (72/batch)
// ---------------------------------------------------------------------------
__global__ __launch_bounds__(NTHR, 1) void scores_mma(
    const __half* __restrict__ Qh, const __half* __restrict__ Ql,
    const __half* __restrict__ Kh, float* __restrict__ Sc)
{
    extern __shared__ __align__(1024) char smem[];
    const int b = blockIdx.z;
    int t = blockIdx.x;
    int mi = 0;
    #pragma unroll
    for (int m = 0; m < 16; m++) {
        int cnt = m / 2 + 1;
        if (t < cnt) { mi = m; break; }
        t -= cnt;
    }
    const int ni = t;
    const int m0 = mi * TM, n0 = ni * TN2;

    const size_t boff = (size_t)b * S * E;
    gemm_core64(Qh + boff, Ql + boff, Kh + boff, m0, n0, E, E, E / KB, smem);
    const float* ep = (const float*)smem;
    float* oF = Sc + (size_t)b * S * S;
    const int tid = threadIdx.x;
    #pragma unroll
    for (int i = 0; i < 32; i++) {
        int idx = tid + NTHR * i;
        int r = idx >> 6, c4 = (idx & 63) * 4;
        float4 o;
        o.x = ep[r * EPIT64 + c4 + 0];
        o.y = ep[r * EPIT64 + c4 + 1];
        o.z = ep[r * EPIT64 + c4 + 2];
        o.w = ep[r * EPIT64 + c4 + 3];
        *(float4*)&oF[(size_t)(m0 + r) * S + n0 + c4] = o;
    }
}

// ---------------------------------------------------------------------------
// attn_out = P @ V (core32), longest m-tiles first
// ---------------------------------------------------------------------------
__global__ __launch_bounds__(NTHR, 1) void attnv_mma(
    const __half* __restrict__ Ph, const __half* __restrict__ Pl,
    const __half* __restrict__ Vth,
    __half* AOh, __half* AOl)
{
    extern __shared__ __align__(1024) char smem[];
    const int b = blockIdx.z;
    const int mi = (gridDim.y - 1) - blockIdx.y;
    const int m0 = mi * TM, n0 = blockIdx.x * TN;
    const size_t poff = (size_t)b * S * S, voff = (size_t)b * E * S;

    gemm_core32(Ph + poff, Pl + poff, Vth + voff,
                m0, n0, S, S, (m0 + TM) / KB, smem);
    const float* ep = (const float*)smem;
    store_pair32(ep, nullptr, 1.0f, AOh + (size_t)b * S * E, AOl + (size_t)b * S * E,
                 m0, n0, E);
}

// ---------------------------------------------------------------------------
// Output projection (core32): out = AO @ Wo^T + bo (fp32)
// ---------------------------------------------------------------------------
__global__ __launch_bounds__(NTHR, 1) void outproj_mma(
    const __half* __restrict__ AOh, const __half* __restrict__ AOl,
    const __half* __restrict__ woh,
    const float* __restrict__ bo, float* __restrict__ out)
{
    extern __shared__ __align__(1024) char smem[];
    const int m0 = blockIdx.y * TM, n0 = blockIdx.x * TN;
    gemm_core32(AOh, AOl, woh, m0, n0, E, E, E / KB, smem);
    const float* ep = (const float*)smem;
    const int tid = threadIdx.x;
    #pragma unroll
    for (int i = 0; i < 16; i++) {
        int idx = tid + NTHR * i;
        int r = idx >> 5, c4 = (idx & 31) * 4;
        float4 bv = *(const float4*)&bo[n0 + c4];
        float4 o;
        o.x = ep[r * EPIT32 + c4 + 0] + bv.x;
        o.y = ep[r * EPIT32 + c4 + 1] + bv.y;
        o.z = ep[r * EPIT32 + c4 + 2] + bv.z;
        o.w = ep[r * EPIT32 + c4 + 3] + bv.w;
        *(float4*)&out[(size_t)(m0 + r) * E + n0 + c4] = o;
    }
}

// ---------------------------------------------------------------------------
// Host launcher
// ---------------------------------------------------------------------------
extern "C" void kernel_launch(void* const* d_in, const int* in_sizes, int n_in,
                              void* d_out, int out_size)
{
    const float* query = (const float*)d_in[0];
    const float* key_  = (const float*)d_in[1];
    const float* value = (const float*)d_in[2];
    const float* Wq = (const float*)d_in[4];
    const float* bq = (const float*)d_in[5];
    const float* Wk = (const float*)d_in[6];
    const float* bk = (const float*)d_in[7];
    const float* Wv = (const float*)d_in[8];
    const float* bv = (const float*)d_in[9];
    const float* Wo = (const float*)d_in[10];
    const float* bo = (const float*)d_in[11];
    float* out = (float*)d_out;

    #define SYM(p, s) void* p; cudaGetSymbolAddress(&p, s)
    SYM(qh, g_qh); SYM(ql, g_ql); SYM(kh, g_kh); SYM(kl, g_kl); SYM(vh, g_vh); SYM(vl, g_vl);
    SYM(wqh, g_wqh); SYM(wkh, g_wkh); SYM(wvh, g_wvh); SYM(woh, g_woh);
    SYM(Qh, g_Qh); SYM(Ql, g_Ql); SYM(Kh, g_Kh); SYM(Vth, g_Vth);
    SYM(Sc, g_Sc); SYM(Ph, g_Ph); SYM(Pl, g_Pl); SYM(AOh, g_AOh); SYM(AOl, g_AOl);
    #undef SYM
    typedef __half hf;

    cudaFuncSetAttribute((const void*)proj_qkv,    cudaFuncAttributeMaxDynamicSharedMemorySize, SMEM32);
    cudaFuncSetAttribute((const void*)scores_mma,  cudaFuncAttributeMaxDynamicSharedMemorySize, SMEM64);
    cudaFuncSetAttribute((const void*)attnv_mma,   cudaFuncAttributeMaxDynamicSharedMemorySize, SMEM32);
    cudaFuncSetAttribute((const void*)outproj_mma, cudaFuncAttributeMaxDynamicSharedMemorySize, SMEM32);

    // 1) fp32 -> fp16 conversions
    const int nIn = M_ROWS * E, nW = E * E;
    cvt3<<<dim3(nIn / 2048, 3), 256>>>(query, key_, value,
        (hf*)qh, (hf*)ql, (hf*)kh, (hf*)kl, (hf*)vh, (hf*)vl);
    cvtw<<<dim3(nW / 2048, 4), 256>>>(Wq, Wk, Wv, Wo,
        (hf*)wqh, (hf*)wkh, (hf*)wvh, (hf*)woh);

    // 2) fused Q/K/V projections (core32)
    proj_qkv<<<dim3(E / TN, M_ROWS / TM, 3), NTHR, SMEM32>>>(
        (hf*)qh, (hf*)ql, (hf*)kh, (hf*)kl, (hf*)vh, (hf*)vl,
        (hf*)wqh, (hf*)wkh, (hf*)wvh,
        bq, bk, bv,
        (hf*)Qh, (hf*)Ql, (hf*)Kh, (hf*)Vth);

    // 3) scores (core64) — 72 triangular tiles per batch
    scores_mma<<<dim3(72, 1, B), NTHR, SMEM64>>>(
        (hf*)Qh, (hf*)Ql, (hf*)Kh, (float*)Sc);

    // 4) fused softmax -> fp16-pair P (longest rows first)
    softmax_pair<<<B * S, 256>>>((const float*)Sc, (hf*)Ph, (hf*)Pl);

    // 5) attn_out = P @ V (core32, longest m-tiles first)
    attnv_mma<<<dim3(E / TN, S / TM, B), NTHR, SMEM32>>>(
        (hf*)Ph, (hf*)Pl, (hf*)Vth, (hf*)AOh, (hf*)AOl);

    // 6) output projection (core32) -> d_out
    outproj_mma<<<dim3(E / TN, M_ROWS / TM, 1), NTHR, SMEM32>>>(
        (hf*)AOh, (hf*)AOl, (hf*)woh, bo, out);
}